// round 4
// baseline (speedup 1.0000x reference)
#include <cuda_runtime.h>
#include <cstdint>

// ---------------------------------------------------------------------------
// CentralCritic via warp-level tf32 mma.sync (plain sm_103 PTX path).
//   enc:    relu(state[B,256] @ encW[256,128] + b) -> g_enc
//   critic: per pair p (20): h = relu([acs_loo(48)|enc(128)] @ W1 + b1)
//           out = h . W2[:, argmax(acs_self)] + b2[c]
// R4: critic = 512 thr / 16 warps (32x32 warp tiles, no reg spills),
//     K-split double-buffered X staging (cp.async overlaps MMA fully).
// ---------------------------------------------------------------------------

#define A_   4
#define H_   3
#define HI_  2
#define C_   16
#define S_   256
#define D_   128
#define IN_  176
#define NPAIR 20
#define NT    4      // 128-row tiles per critic CTA
#define NTE   4      // 64-row tiles per enc CTA
#define KH    88     // K half
#define KSH   11     // k-steps per half

// smem strides (floats), conflict-free fragment loads
#define XS_ST  92    // critic X half rows (88 + pad): bank = 28g+t, distinct
#define WS_ST  136   // W rows (128 + pad): bank = 8t+g, distinct
#define XE_ST  260   // enc X rows (256 + pad)

// critic smem offsets (floats)
#define WS_OFF   0                       // 176*136 = 23936
#define X0_OFF   23936                   // 128*92  = 11776
#define X1_OFF   35712                   // 128*92  = 11776
#define W2_OFF   47488                   // 128*17  = 2176
#define B1_OFF   49664                   // 128
#define B2_OFF   49792                   // 16
#define PART_OFF 49808                   // 4*128 = 512
#define CIDX_OFF 50320                   // 128
#define K_SMEMB  (50448 * 4)             // 201792 B

// enc smem offsets (floats)
#define WSE_OFF  0                       // 256*136 = 34816
#define XSE_OFF  34816                   // 64*260  = 16640
#define BE_OFF   51456                   // 128
#define E_SMEMB  (51584 * 4)

__device__ float g_enc[32768 * D_];

__constant__ int c_loo[4][3] = {{1,2,3},{0,2,3},{0,1,3},{0,1,2}};

// ---- helpers ---------------------------------------------------------------
__device__ __forceinline__ uint32_t smem_u32(const void* p) {
    uint32_t r;
    asm("{ .reg .u64 t; cvta.to.shared.u64 t, %1; cvt.u32.u64 %0, t; }"
        : "=r"(r) : "l"(p));
    return r;
}
__device__ __forceinline__ uint32_t tf32r(float x) {
    uint32_t y; asm("cvt.rna.tf32.f32 %0, %1;" : "=r"(y) : "f"(x)); return y;
}
__device__ __forceinline__ void cpasync16(uint32_t dst, const void* src) {
    asm volatile("cp.async.cg.shared.global [%0], [%1], 16;"
                 :: "r"(dst), "l"(src));
}
#define CPCOMMIT()  asm volatile("cp.async.commit_group;" ::: "memory")
#define CPWAITG(n)  asm volatile("cp.async.wait_group %0;" :: "n"(n) : "memory")

__device__ __forceinline__ void mma8(float* d, const uint32_t* a,
                                     const uint32_t* b) {
    asm volatile(
        "mma.sync.aligned.m16n8k8.row.col.f32.tf32.tf32.f32 "
        "{%0,%1,%2,%3}, {%4,%5,%6,%7}, {%8,%9}, {%0,%1,%2,%3};"
        : "+f"(d[0]), "+f"(d[1]), "+f"(d[2]), "+f"(d[3])
        : "r"(a[0]), "r"(a[1]), "r"(a[2]), "r"(a[3]), "r"(b[0]), "r"(b[1]));
}

// ---------------------------------------------------------------------------
// encoder: [B,256] @ [256,128] + bias, relu -> g_enc.  (unchanged from R3)
// ---------------------------------------------------------------------------
__global__ __launch_bounds__(256, 1) void enc_kernel(
    const float* __restrict__ state, const float* __restrict__ encW,
    const float* __restrict__ encb, int B)
{
    extern __shared__ float smf[];
    const int tid = threadIdx.x, wid = tid >> 5, lane = tid & 31;
    const int g = lane >> 2, t = lane & 3;
    const int wm = wid >> 2, wn = wid & 3;
    const int wr = wm * 32, wc = wn * 32;

    for (int it = 0; it < 32; it++) {
        int fi = it * 256 + tid;
        int k = fi >> 5, n4 = fi & 31;
        float4 v = *(const float4*)(encW + (size_t)k * D_ + n4 * 4);
        uint4 w; w.x = tf32r(v.x); w.y = tf32r(v.y);
        w.z = tf32r(v.z); w.w = tf32r(v.w);
        *(uint4*)(smf + WSE_OFF + k * WS_ST + n4 * 4) = w;
    }
    if (tid < D_) smf[BE_OFF + tid] = encb[tid];

    const uint32_t xbase = smem_u32(smf + XSE_OFF);
    const int tile0 = blockIdx.x * NTE;

    {
        int row0 = tile0 * 64;
        for (int it = 0; it < 16; it++) {
            int idx = it * 256 + tid;
            int c = idx & 63, row = idx >> 6;
            cpasync16(xbase + (uint32_t)(row * XE_ST + c * 4) * 4,
                      state + (size_t)(row0 + row) * S_ + c * 4);
        }
        CPCOMMIT();
    }
    CPWAITG(0);
    __syncthreads();

    for (int tt = 0; tt < NTE; tt++) {
        const int row0 = (tile0 + tt) * 64;
        float acc[2][4][4];
#pragma unroll
        for (int mi = 0; mi < 2; mi++)
#pragma unroll
            for (int ni = 0; ni < 4; ni++)
#pragma unroll
                for (int e = 0; e < 4; e++) acc[mi][ni][e] = 0.f;

        const uint32_t* Xu = (const uint32_t*)(smf + XSE_OFF);
        const uint32_t* Wu = (const uint32_t*)(smf + WSE_OFF);
#pragma unroll
        for (int ks = 0; ks < 32; ks++) {
            const int k0 = ks * 8;
            uint32_t a[2][4], b[4][2];
#pragma unroll
            for (int mi = 0; mi < 2; mi++) {
                int r = wr + mi * 16 + g;
                a[mi][0] = Xu[r * XE_ST + k0 + t];
                a[mi][1] = Xu[(r + 8) * XE_ST + k0 + t];
                a[mi][2] = Xu[r * XE_ST + k0 + t + 4];
                a[mi][3] = Xu[(r + 8) * XE_ST + k0 + t + 4];
            }
#pragma unroll
            for (int ni = 0; ni < 4; ni++) {
                int n = wc + ni * 8 + g;
                b[ni][0] = Wu[(k0 + t) * WS_ST + n];
                b[ni][1] = Wu[(k0 + t + 4) * WS_ST + n];
            }
#pragma unroll
            for (int mi = 0; mi < 2; mi++)
#pragma unroll
                for (int ni = 0; ni < 4; ni++)
                    mma8(acc[mi][ni], a[mi], b[ni]);
        }
        __syncthreads();

        if (tt + 1 < NTE) {
            int nrow0 = (tile0 + tt + 1) * 64;
            for (int it = 0; it < 16; it++) {
                int idx = it * 256 + tid;
                int c = idx & 63, row = idx >> 6;
                cpasync16(xbase + (uint32_t)(row * XE_ST + c * 4) * 4,
                          state + (size_t)(nrow0 + row) * S_ + c * 4);
            }
            CPCOMMIT();
        }

#pragma unroll
        for (int mi = 0; mi < 2; mi++) {
            int r0 = row0 + wr + mi * 16 + g;
#pragma unroll
            for (int ni = 0; ni < 4; ni++) {
                int col = wc + ni * 8 + 2 * t;
                float b0 = smf[BE_OFF + col], b1v = smf[BE_OFF + col + 1];
                float2 o0, o1;
                o0.x = fmaxf(acc[mi][ni][0] + b0, 0.f);
                o0.y = fmaxf(acc[mi][ni][1] + b1v, 0.f);
                o1.x = fmaxf(acc[mi][ni][2] + b0, 0.f);
                o1.y = fmaxf(acc[mi][ni][3] + b1v, 0.f);
                *(float2*)(g_enc + (size_t)r0 * D_ + col) = o0;
                *(float2*)(g_enc + (size_t)(r0 + 8) * D_ + col) = o1;
            }
        }

        if (tt + 1 < NTE) CPWAITG(0);
        __syncthreads();
    }
}

// ---------------------------------------------------------------------------
// critic: 512 thr, 16 warps (4x4), warp tile 32x32, K-half double buffering.
// ---------------------------------------------------------------------------
__global__ __launch_bounds__(512, 1) void critic_kernel(
    const float* __restrict__ acs,
    const float* __restrict__ eW1, const float* __restrict__ eb1,
    const float* __restrict__ eW2, const float* __restrict__ eb2,
    const float* __restrict__ iW1, const float* __restrict__ ib1,
    const float* __restrict__ iW2, const float* __restrict__ ib2,
    float* __restrict__ out, int B)
{
    extern __shared__ float smf[];
    const int tid = threadIdx.x, wid = tid >> 5, lane = tid & 31;
    const int g = lane >> 2, t = lane & 3;
    const int wm = wid >> 2, wn = wid & 3;
    const int wr = wm * 32, wc = wn * 32;
    const int p = blockIdx.y;

    int i, head;
    const float *W1, *b1, *W2, *b2;
    float* outp;
    if (p < A_ * H_) {
        i = p / H_; int j = p % H_; head = j;
        W1 = eW1 + (size_t)(j * A_ + i) * IN_ * D_;
        b1 = eb1 + (size_t)(j * A_ + i) * D_;
        W2 = eW2 + (size_t)(j * A_ + i) * D_ * C_;
        b2 = eb2 + (size_t)(j * A_ + i) * C_;
        outp = out + (size_t)p * B;
    } else {
        int q = p - A_ * H_;
        i = q / HI_; int j = q % HI_; head = j + 1;
        W1 = iW1 + (size_t)(j * A_ + i) * IN_ * D_;
        b1 = ib1 + (size_t)(j * A_ + i) * D_;
        W2 = iW2 + (size_t)(j * A_ + i) * D_ * C_;
        b2 = ib2 + (size_t)(j * A_ + i) * C_;
        outp = out + (size_t)(A_ * H_) * B + (size_t)q * B;
    }
    const float* acsA[3];
    acsA[0] = acs + (size_t)(c_loo[i][0] * H_ + head) * B * C_;
    acsA[1] = acs + (size_t)(c_loo[i][1] * H_ + head) * B * C_;
    acsA[2] = acs + (size_t)(c_loo[i][2] * H_ + head) * B * C_;
    const float* acsSelf = acs + (size_t)(i * H_ + head) * B * C_;

    // ---- stage W1 (cvt.rna), W2 (stride 17), b1, b2 ----
    for (int it = 0; it < 11; it++) {
        int fi = it * 512 + tid;            // 5632 float4
        int k = fi >> 5, n4 = fi & 31;
        float4 v = *(const float4*)(W1 + (size_t)k * D_ + n4 * 4);
        uint4 w; w.x = tf32r(v.x); w.y = tf32r(v.y);
        w.z = tf32r(v.z); w.w = tf32r(v.w);
        *(uint4*)(smf + WS_OFF + k * WS_ST + n4 * 4) = w;
    }
    for (int it = 0; it < 4; it++) {
        int idx = it * 512 + tid;           // 2048 floats
        int d = idx >> 4, c = idx & 15;
        smf[W2_OFF + d * 17 + c] = W2[idx];
    }
    if (tid < D_) smf[B1_OFF + tid] = b1[tid];
    if (tid < C_) smf[B2_OFF + tid] = b2[tid];

    const uint32_t x0b = smem_u32(smf + X0_OFF);
    const uint32_t x1b = smem_u32(smf + X1_OFF);
    const int tile0 = blockIdx.x * NT;
    int* cidx = (int*)(smf + CIDX_OFF);

    // staging lambdas (2816 chunks of 16B per half, 512 threads, 6 iters)
    auto stage_half0 = [&](int row0) {
#pragma unroll
        for (int it = 0; it < 6; it++) {
            int idx = it * 512 + tid;
            if (idx < 2816) {
                int row = idx / 22, c = idx - (idx / 22) * 22;
                const void* src;
                if (c < 12)
                    src = acsA[c >> 2] + (size_t)(row0 + row) * C_ + (c & 3) * 4;
                else
                    src = g_enc + (size_t)(row0 + row) * D_ + (c - 12) * 4;
                cpasync16(x0b + (uint32_t)(row * XS_ST + c * 4) * 4, src);
            }
        }
        CPCOMMIT();
    };
    auto stage_half1 = [&](int row0) {
#pragma unroll
        for (int it = 0; it < 6; it++) {
            int idx = it * 512 + tid;
            if (idx < 2816) {
                int row = idx / 22, c = idx - (idx / 22) * 22;
                const void* src = g_enc + (size_t)(row0 + row) * D_ + 40 + c * 4;
                cpasync16(x1b + (uint32_t)(row * XS_ST + c * 4) * 4, src);
            }
        }
        CPCOMMIT();
    };

    // prologue
    stage_half0(tile0 * 128);
    stage_half1(tile0 * 128);

    for (int tt = 0; tt < NT; tt++) {
        const int row0 = (tile0 + tt) * 128;
        float acc[2][4][4];
#pragma unroll
        for (int mi = 0; mi < 2; mi++)
#pragma unroll
            for (int ni = 0; ni < 4; ni++)
#pragma unroll
                for (int e = 0; e < 4; e++) acc[mi][ni][e] = 0.f;

        const uint32_t* Wu = (const uint32_t*)(smf + WS_OFF);

        // ---- half 0 ----
        CPWAITG(1);            // S(tt,0) complete
        __syncthreads();
        {
            const uint32_t* Xu = (const uint32_t*)(smf + X0_OFF);
#pragma unroll
            for (int ks = 0; ks < KSH; ks++) {
                const int k0 = ks * 8;
                uint32_t a[2][4], b[4][2];
#pragma unroll
                for (int mi = 0; mi < 2; mi++) {
                    int r = wr + mi * 16 + g;
                    a[mi][0] = Xu[r * XS_ST + k0 + t];
                    a[mi][1] = Xu[(r + 8) * XS_ST + k0 + t];
                    a[mi][2] = Xu[r * XS_ST + k0 + t + 4];
                    a[mi][3] = Xu[(r + 8) * XS_ST + k0 + t + 4];
                }
#pragma unroll
                for (int ni = 0; ni < 4; ni++) {
                    int n = wc + ni * 8 + g;
                    b[ni][0] = Wu[(k0 + t) * WS_ST + n];
                    b[ni][1] = Wu[(k0 + t + 4) * WS_ST + n];
                }
#pragma unroll
                for (int mi = 0; mi < 2; mi++)
#pragma unroll
                    for (int ni = 0; ni < 4; ni++)
                        mma8(acc[mi][ni], a[mi], b[ni]);
            }
        }
        __syncthreads();       // buf0 consumed
        if (tt + 1 < NT) stage_half0((tile0 + tt + 1) * 128);

        // ---- half 1 ----
        if (tt + 1 < NT) { CPWAITG(1); } else { CPWAITG(0); }  // S(tt,1) done
        __syncthreads();
        {
            const uint32_t* Xu = (const uint32_t*)(smf + X1_OFF);
#pragma unroll
            for (int ks = 0; ks < KSH; ks++) {
                const int k0 = ks * 8;
                const int kw = KH + k0;
                uint32_t a[2][4], b[4][2];
#pragma unroll
                for (int mi = 0; mi < 2; mi++) {
                    int r = wr + mi * 16 + g;
                    a[mi][0] = Xu[r * XS_ST + k0 + t];
                    a[mi][1] = Xu[(r + 8) * XS_ST + k0 + t];
                    a[mi][2] = Xu[r * XS_ST + k0 + t + 4];
                    a[mi][3] = Xu[(r + 8) * XS_ST + k0 + t + 4];
                }
#pragma unroll
                for (int ni = 0; ni < 4; ni++) {
                    int n = wc + ni * 8 + g;
                    b[ni][0] = Wu[(kw + t) * WS_ST + n];
                    b[ni][1] = Wu[(kw + t + 4) * WS_ST + n];
                }
#pragma unroll
                for (int mi = 0; mi < 2; mi++)
#pragma unroll
                    for (int ni = 0; ni < 4; ni++)
                        mma8(acc[mi][ni], a[mi], b[ni]);
            }
        }
        // argmax for this tile (overlaps tail of MMA wavefronts)
        if (tid < 128) {
            const float* ar = acsSelf + (size_t)(row0 + tid) * C_;
            float best = ar[0]; int c = 0;
#pragma unroll
            for (int cc = 1; cc < C_; cc++) {
                float v = ar[cc];
                if (v > best) { best = v; c = cc; }
            }
            cidx[tid] = c;
        }
        __syncthreads();       // buf1 consumed + cidx visible
        if (tt + 1 < NT) stage_half1((tile0 + tt + 1) * 128);

        // ---- epilogue: relu(acc+b1) . W2[:,c], 4-way N reduction ----
#pragma unroll
        for (int mi = 0; mi < 2; mi++) {
            int r0 = wr + mi * 16 + g;
            int cR0 = cidx[r0], cR1 = cidx[r0 + 8];
            float s0 = 0.f, s1 = 0.f;
#pragma unroll
            for (int ni = 0; ni < 4; ni++) {
                int col0 = wc + ni * 8 + 2 * t;
                float bb0 = smf[B1_OFF + col0], bb1 = smf[B1_OFF + col0 + 1];
                float w00 = smf[W2_OFF + col0 * 17 + cR0];
                float w01 = smf[W2_OFF + (col0 + 1) * 17 + cR0];
                float w10 = smf[W2_OFF + col0 * 17 + cR1];
                float w11 = smf[W2_OFF + (col0 + 1) * 17 + cR1];
                s0 += fmaxf(acc[mi][ni][0] + bb0, 0.f) * w00
                    + fmaxf(acc[mi][ni][1] + bb1, 0.f) * w01;
                s1 += fmaxf(acc[mi][ni][2] + bb0, 0.f) * w10
                    + fmaxf(acc[mi][ni][3] + bb1, 0.f) * w11;
            }
            s0 += __shfl_xor_sync(0xffffffffu, s0, 1);
            s0 += __shfl_xor_sync(0xffffffffu, s0, 2);
            s1 += __shfl_xor_sync(0xffffffffu, s1, 1);
            s1 += __shfl_xor_sync(0xffffffffu, s1, 2);
            if (t == 0) {
                smf[PART_OFF + wn * 128 + r0] = s0;
                smf[PART_OFF + wn * 128 + r0 + 8] = s1;
            }
        }
        __syncthreads();
        if (tid < 128) {
            float q = smf[PART_OFF + tid] + smf[PART_OFF + 128 + tid]
                    + smf[PART_OFF + 256 + tid] + smf[PART_OFF + 384 + tid]
                    + smf[B2_OFF + cidx[tid]];
            outp[row0 + tid] = q;
        }
        __syncthreads();       // PART reusable next tile
    }
}

// ---------------------------------------------------------------------------
extern "C" void kernel_launch(void* const* d_in, const int* in_sizes, int n_in,
                              void* d_out, int out_size)
{
    const float* state = (const float*)d_in[0];
    const float* acs   = (const float*)d_in[1];
    const float* encW  = (const float*)d_in[2];
    const float* encb  = (const float*)d_in[3];
    const float* eW1   = (const float*)d_in[4];
    const float* eb1   = (const float*)d_in[5];
    const float* eW2   = (const float*)d_in[6];
    const float* eb2   = (const float*)d_in[7];
    const float* iW1   = (const float*)d_in[8];
    const float* ib1   = (const float*)d_in[9];
    const float* iW2   = (const float*)d_in[10];
    const float* ib2   = (const float*)d_in[11];
    float* out = (float*)d_out;

    const int B = in_sizes[0] / S_;          // 32768

    static int inited = 0;
    if (!inited) {
        cudaFuncSetAttribute(enc_kernel,
            cudaFuncAttributeMaxDynamicSharedMemorySize, E_SMEMB);
        cudaFuncSetAttribute(critic_kernel,
            cudaFuncAttributeMaxDynamicSharedMemorySize, K_SMEMB);
        inited = 1;
    }

    enc_kernel<<<B / 64 / NTE, 256, E_SMEMB>>>(state, encW, encb, B);

    dim3 grid(B / 128 / NT, NPAIR);
    critic_kernel<<<grid, 512, K_SMEMB>>>(acs, eW1, eb1, eW2, eb2,
                                          iW1, ib1, iW2, ib2, out, B);
}